// round 15
// baseline (speedup 1.0000x reference)
#include <cuda_runtime.h>

#define NN 50000
#define EE 800000
#define ET 850000   // EE + NN self loops
#define HID 96
#define NEG 0.2f

#define SCAN_TPB 256
#define SCAN_BLOCKS ((NN + SCAN_TPB - 1) / SCAN_TPB)   // 196

// ---------------- scratch (no cudaMalloc allowed) ----------------
__device__ float g_h[NN * HID];
__device__ float g_bufA[NN * HID];
__device__ float g_bufB[NN * HID];
__device__ float g_es[NN];
__device__ float g_ed[NN];
__device__ float2 g_hesf[NN];       // (hf, esf) packed for fagg
__device__ float g_edf[NN];
__device__ unsigned g_max_u[4];     // ordered-float max: slots 0-2 = es per layer, 3 = esf
__device__ int   g_cnt[NN];         // ALWAYS zero at launch entry (module init + scanout self-clean)
__device__ int   g_rowptr[NN + 1];
__device__ int   g_fill[NN];
__device__ int   g_srcbuf[ET];
__device__ int   g_bsum[SCAN_BLOCKS];
__device__ int   g_is64;

__device__ __forceinline__ float* sel_buf(int s) {
    return (s == 1) ? g_bufA : g_bufB;
}

// order-preserving float <-> uint encoding (for atomicMax on floats)
__device__ __forceinline__ unsigned fenc(float f) {
    unsigned u = __float_as_uint(f);
    return (u & 0x80000000u) ? ~u : (u | 0x80000000u);
}
__device__ __forceinline__ float fdec(unsigned e) {
    unsigned u = (e & 0x80000000u) ? (e & 0x7FFFFFFFu) : ~e;
    return __uint_as_float(u);
}

// ---------------- reset: dtype probe + max slots (1 block; must precede gemm0) ----------------
__global__ void rst_kernel(const int* __restrict__ ei32) {
    __shared__ int nz;
    if (threadIdx.x == 0) nz = 0;
    __syncthreads();
    if (ei32[2 * threadIdx.x + 1] != 0) nz = 1;  // benign race
    __syncthreads();
    if (threadIdx.x == 0) g_is64 = (nz == 0) ? 1 : 0;
    if (threadIdx.x < 4) g_max_u[threadIdx.x] = fenc(-1e30f);
}

__device__ __forceinline__ int load_idx(const void* ei, long long pos) {
    if (g_is64) return (int)((const long long*)ei)[pos];
    return ((const int*)ei)[pos];
}

// ---------------- CSR build ----------------
// 4 edges per thread, vectorized loads. EE and ET-EE are divisible by 4, so
// no thread straddles the real-edge / self-loop boundary.
__global__ void hist_kernel(const void* __restrict__ ei) {
    int t = blockIdx.x * blockDim.x + threadIdx.x;
    int j = t * 4;
    if (j >= ET) return;
    int d0, d1, d2, d3;
    if (j < EE) {
        if (g_is64) {
            const longlong2* p = (const longlong2*)((const long long*)ei + EE + j);
            longlong2 a = p[0], c = p[1];
            d0 = (int)a.x; d1 = (int)a.y; d2 = (int)c.x; d3 = (int)c.y;
        } else {
            int4 d4 = *(const int4*)((const int*)ei + EE + j);
            d0 = d4.x; d1 = d4.y; d2 = d4.z; d3 = d4.w;
        }
    } else {
        d0 = j - EE; d1 = d0 + 1; d2 = d0 + 2; d3 = d0 + 3;
    }
    atomicAdd(&g_cnt[d0], 1);
    atomicAdd(&g_cnt[d1], 1);
    atomicAdd(&g_cnt[d2], 1);
    atomicAdd(&g_cnt[d3], 1);
}

__global__ void bsum_kernel() {
    __shared__ int wsum[8];
    int t = threadIdx.x;
    int lane = t & 31, wid = t >> 5;
    int i = blockIdx.x * SCAN_TPB + t;
    int v = (i < NN) ? g_cnt[i] : 0;
#pragma unroll
    for (int off = 16; off; off >>= 1)
        v += __shfl_xor_sync(0xFFFFFFFFu, v, off);
    if (lane == 0) wsum[wid] = v;
    __syncthreads();
    if (t == 0) {
        int s = wsum[0];
#pragma unroll
        for (int w = 1; w < 8; w++) s += wsum[w];
        g_bsum[blockIdx.x] = s;
    }
}

__global__ void scanout_kernel() {
    __shared__ int woff[8];
    __shared__ int wtot[8];
    int t = threadIdx.x;
    int lane = t & 31, wid = t >> 5;

    // block offset = sum of g_bsum[0 .. blockIdx-1]  (shuffle reduce)
    int v = (t < blockIdx.x && t < SCAN_BLOCKS) ? g_bsum[t] : 0;
#pragma unroll
    for (int off = 16; off; off >>= 1)
        v += __shfl_xor_sync(0xFFFFFFFFu, v, off);
    if (lane == 0) woff[wid] = v;

    // per-thread count + warp inclusive scan
    int i = blockIdx.x * SCAN_TPB + t;
    int c = (i < NN) ? g_cnt[i] : 0;
    if (i < NN) g_cnt[i] = 0;   // self-clean: keeps "g_cnt==0 at entry" invariant
    int sc = c;
#pragma unroll
    for (int d = 1; d < 32; d <<= 1) {
        int n = __shfl_up_sync(0xFFFFFFFFu, sc, d);
        if (lane >= d) sc += n;
    }
    if (lane == 31) wtot[wid] = sc;
    __syncthreads();

    int offset = woff[0];
#pragma unroll
    for (int w = 1; w < 8; w++) offset += woff[w];
    int add = 0;
    for (int w = 0; w < wid; w++) add += wtot[w];

    int excl = sc - c + add + offset;
    if (i < NN) {
        g_rowptr[i] = excl;
        g_fill[i]   = excl;
    }
    if (i == NN - 1) g_rowptr[NN] = ET;
}

__global__ void scatter_kernel(const void* __restrict__ ei) {
    int t = blockIdx.x * blockDim.x + threadIdx.x;
    int j = t * 4;
    if (j >= ET) return;
    int s0, s1, s2, s3, d0, d1, d2, d3;
    if (j < EE) {
        if (g_is64) {
            const longlong2* ps = (const longlong2*)((const long long*)ei + j);
            const longlong2* pd = (const longlong2*)((const long long*)ei + EE + j);
            longlong2 a = ps[0], c = ps[1];
            s0 = (int)a.x; s1 = (int)a.y; s2 = (int)c.x; s3 = (int)c.y;
            a = pd[0]; c = pd[1];
            d0 = (int)a.x; d1 = (int)a.y; d2 = (int)c.x; d3 = (int)c.y;
        } else {
            int4 sv = *(const int4*)((const int*)ei + j);
            int4 dv = *(const int4*)((const int*)ei + EE + j);
            s0 = sv.x; s1 = sv.y; s2 = sv.z; s3 = sv.w;
            d0 = dv.x; d1 = dv.y; d2 = dv.z; d3 = dv.w;
        }
    } else {
        s0 = d0 = j - EE; s1 = d1 = d0 + 1; s2 = d2 = d0 + 2; s3 = d3 = d0 + 3;
    }
    g_srcbuf[atomicAdd(&g_fill[d0], 1)] = s0;
    g_srcbuf[atomicAdd(&g_fill[d1], 1)] = s1;
    g_srcbuf[atomicAdd(&g_fill[d2], 1)] = s2;
    g_srcbuf[atomicAdd(&g_fill[d3], 1)] = s3;
}

// ---------------- GEMM + fused es/ed: 8 nodes/block, 96 threads, f32x2 ----------------
template <int IN>
__global__ void gemm_kernel(const float* __restrict__ x, int in_sel,
                            const float* __restrict__ W,
                            const float* __restrict__ as, const float* __restrict__ ad,
                            int slot) {
    __shared__ __align__(16) float2 xs[IN][4];   // [k][pair]; pair p = nodes (2p, 2p+1)
    __shared__ __align__(16) float sh_h[8][HID];
    __shared__ float sred[3];
    const float* in = (in_sel == 0) ? x : sel_buf(in_sel);
    int nb = blockIdx.x * 8;
    int o  = threadIdx.x;   // 0..95
    int lane = o & 31, wid = o >> 5;
    // float4 input loads: 8*IN/4 vectors striped over 96 threads
    for (int idx = o; idx < 8 * (IN / 4); idx += HID) {
        int n = idx / (IN / 4), c4 = idx % (IN / 4);
        float4 v = ((const float4*)(in + (nb + n) * IN))[c4];
        int p = n >> 1, half = n & 1;
        ((float*)&xs[c4 * 4 + 0][p])[half] = v.x;
        ((float*)&xs[c4 * 4 + 1][p])[half] = v.y;
        ((float*)&xs[c4 * 4 + 2][p])[half] = v.z;
        ((float*)&xs[c4 * 4 + 3][p])[half] = v.w;
    }
    __syncthreads();

    unsigned long long acc0 = 0ull, acc1 = 0ull, acc2 = 0ull, acc3 = 0ull;
#pragma unroll 8
    for (int k = 0; k < IN; k++) {
        float w = W[k * HID + o];
        unsigned long long ww;
        asm("mov.b64 %0, {%1, %1};" : "=l"(ww) : "r"(__float_as_uint(w)));
        ulonglong2 X01 = *reinterpret_cast<const ulonglong2*>(&xs[k][0]);
        ulonglong2 X23 = *reinterpret_cast<const ulonglong2*>(&xs[k][2]);
        asm("fma.rn.f32x2 %0, %1, %2, %0;" : "+l"(acc0) : "l"(X01.x), "l"(ww));
        asm("fma.rn.f32x2 %0, %1, %2, %0;" : "+l"(acc1) : "l"(X01.y), "l"(ww));
        asm("fma.rn.f32x2 %0, %1, %2, %0;" : "+l"(acc2) : "l"(X23.x), "l"(ww));
        asm("fma.rn.f32x2 %0, %1, %2, %0;" : "+l"(acc3) : "l"(X23.y), "l"(ww));
    }

    float h0 = __uint_as_float((unsigned)acc0);
    float h1 = __uint_as_float((unsigned)(acc0 >> 32));
    float h2 = __uint_as_float((unsigned)acc1);
    float h3 = __uint_as_float((unsigned)(acc1 >> 32));
    float h4 = __uint_as_float((unsigned)acc2);
    float h5 = __uint_as_float((unsigned)(acc2 >> 32));
    float h6 = __uint_as_float((unsigned)acc3);
    float h7 = __uint_as_float((unsigned)(acc3 >> 32));
    g_h[(nb + 0) * HID + o] = h0;  sh_h[0][o] = h0;
    g_h[(nb + 1) * HID + o] = h1;  sh_h[1][o] = h1;
    g_h[(nb + 2) * HID + o] = h2;  sh_h[2][o] = h2;
    g_h[(nb + 3) * HID + o] = h3;  sh_h[3][o] = h3;
    g_h[(nb + 4) * HID + o] = h4;  sh_h[4][o] = h4;
    g_h[(nb + 5) * HID + o] = h5;  sh_h[5][o] = h5;
    g_h[(nb + 6) * HID + o] = h6;  sh_h[6][o] = h6;
    g_h[(nb + 7) * HID + o] = h7;  sh_h[7][o] = h7;
    __syncthreads();

    // fused es/ed (warp wid handles nodes wid, wid+3, wid+6)
    float4 a4 = make_float4(0.f, 0.f, 0.f, 0.f), d4 = a4;
    if (lane < 24) {
        a4 = ((const float4*)as)[lane];
        d4 = ((const float4*)ad)[lane];
    }
    float wmax = -1e30f;
    for (int n = wid; n < 8; n += 3) {
        float vs = 0.f, vd = 0.f;
        if (lane < 24) {
            float4 hv = *(const float4*)&sh_h[n][lane * 4];
            vs = hv.x * a4.x + hv.y * a4.y + hv.z * a4.z + hv.w * a4.w;
            vd = hv.x * d4.x + hv.y * d4.y + hv.z * d4.z + hv.w * d4.w;
        }
#pragma unroll
        for (int off = 16; off; off >>= 1) {
            vs += __shfl_xor_sync(0xFFFFFFFFu, vs, off);
            vd += __shfl_xor_sync(0xFFFFFFFFu, vd, off);
        }
        if (lane == 0) {
            g_es[nb + n] = vs;
            g_ed[nb + n] = vd;
            wmax = fmaxf(wmax, vs);
        }
    }
    if (lane == 0) sred[wid] = wmax;
    __syncthreads();
    if (o == 0)
        atomicMax(&g_max_u[slot], fenc(fmaxf(fmaxf(sred[0], sred[1]), sred[2])));
}

// ---------------- aggregation: one warp per destination node (no max pass) ----------------
template <bool RESID, bool FINAL>
__global__ void agg_kernel(const float* __restrict__ b, int resid_sel, int out_sel,
                           int slot,
                           const float* __restrict__ Wf,
                           const float* __restrict__ asf,
                           const float* __restrict__ adf) {
    int node = (blockIdx.x * blockDim.x + threadIdx.x) >> 5;
    int lane = threadIdx.x & 31;
    int beg = g_rowptr[node], end = g_rowptr[node + 1];
    float edst = g_ed[node];
    float m = fdec(g_max_u[slot]) + edst;
    m = (m > 0.f) ? m : NEG * m;

    float a0 = 0.f, a1 = 0.f, a2 = 0.f, ssum = 0.f;
#pragma unroll 4
    for (int j = beg; j < end; j++) {
        int s = g_srcbuf[j];                 // broadcast load
        float e = g_es[s] + edst;            // broadcast load
        e = (e > 0.f) ? e : NEG * e;
        float ex = __expf(e - m);
        const float* hp = g_h + s * HID;
        ssum += ex;
        a0 += ex * hp[lane];
        a1 += ex * hp[lane + 32];
        a2 += ex * hp[lane + 64];
    }
    float inv = 1.f / ssum;
    float o0 = a0 * inv + b[lane];
    float o1 = a1 * inv + b[lane + 32];
    float o2 = a2 * inv + b[lane + 64];
    if (RESID) {
        const float* rp = sel_buf(resid_sel) + node * HID;
        o0 += rp[lane]; o1 += rp[lane + 32]; o2 += rp[lane + 64];
    }
    o0 = fmaxf(o0, 0.f); o1 = fmaxf(o1, 0.f); o2 = fmaxf(o2, 0.f);
    if (FINAL) {
        __shared__ float smaxf[8];
        float v = o0 * Wf[lane] + o1 * Wf[lane + 32] + o2 * Wf[lane + 64];
#pragma unroll
        for (int off = 16; off; off >>= 1)
            v += __shfl_xor_sync(0xFFFFFFFFu, v, off);
        float esf = v * asf[0];
        if (lane == 0) {
            g_hesf[node] = make_float2(v, esf);
            g_edf[node]  = v * adf[0];
            smaxf[threadIdx.x >> 5] = esf;
        }
        __syncthreads();
        if (threadIdx.x == 0) {
            float mm = smaxf[0];
#pragma unroll
            for (int i = 1; i < 8; i++) mm = fmaxf(mm, smaxf[i]);
            atomicMax(&g_max_u[3], fenc(mm));
        }
    } else {
        float* op = sel_buf(out_sel) + node * HID;
        op[lane] = o0; op[lane + 32] = o1; op[lane + 64] = o2;
    }
}

// ---------------- final aggregation (out dim = 1, no max pass, packed gather) ----------------
__global__ void fagg_kernel(const float* __restrict__ bf, float* __restrict__ out) {
    int node = (blockIdx.x * blockDim.x + threadIdx.x) >> 5;
    int lane = threadIdx.x & 31;
    if (node >= NN) return;
    int beg = g_rowptr[node], end = g_rowptr[node + 1];
    float edst = g_edf[node];
    float m = fdec(g_max_u[3]) + edst;
    m = (m > 0.f) ? m : NEG * m;

    float ssum = 0.f, wsum = 0.f;
    for (int j = beg + lane; j < end; j += 32) {
        int s = g_srcbuf[j];
        float2 he = g_hesf[s];               // one LDG.64: (hf, esf)
        float e = he.y + edst;
        e = (e > 0.f) ? e : NEG * e;
        float ex = __expf(e - m);
        ssum += ex;
        wsum += ex * he.x;
    }
#pragma unroll
    for (int off = 16; off; off >>= 1) {
        ssum += __shfl_xor_sync(0xFFFFFFFFu, ssum, off);
        wsum += __shfl_xor_sync(0xFFFFFFFFu, wsum, off);
    }
    if (lane == 0) out[node] = wsum / ssum + bf[0];
}

// ---------------- launch ----------------
extern "C" void kernel_launch(void* const* d_in, const int* in_sizes, int n_in,
                              void* d_out, int out_size) {
    const float* x   = (const float*)d_in[0];
    const void*  ei  = d_in[1];
    const float* W0  = (const float*)d_in[3];
    const float* as0 = (const float*)d_in[4];
    const float* ad0 = (const float*)d_in[5];
    const float* b0  = (const float*)d_in[6];
    const float* W1  = (const float*)d_in[7];
    const float* as1 = (const float*)d_in[8];
    const float* ad1 = (const float*)d_in[9];
    const float* b1  = (const float*)d_in[10];
    const float* W2  = (const float*)d_in[11];
    const float* as2 = (const float*)d_in[12];
    const float* ad2 = (const float*)d_in[13];
    const float* b2  = (const float*)d_in[14];
    const float* Wf  = (const float*)d_in[15];
    const float* asf = (const float*)d_in[16];
    const float* adf = (const float*)d_in[17];
    const float* bf  = (const float*)d_in[18];
    float* out = (float*)d_out;

    // lazily-created side stream + fork/join events
    static cudaStream_t s2 = nullptr;
    static cudaEvent_t ev_fork = nullptr, ev_join = nullptr;
    if (s2 == nullptr) {
        cudaStreamCreateWithFlags(&s2, cudaStreamNonBlocking);
        cudaEventCreateWithFlags(&ev_fork, cudaEventDisableTiming);
        cudaEventCreateWithFlags(&ev_join, cudaEventDisableTiming);
    }

    const int TPB = 256;
    const int edge4_blocks = (ET / 4 + TPB - 1) / TPB;
    const int node_warp_blocks = (NN * 32 + TPB - 1) / TPB;   // 6250, exact

    // probe + max-slot reset (must precede gemm0's atomicMax AND the CSR chain)
    rst_kernel<<<1, 256>>>((const int*)ei);

    // fork: CSR build on s2, gemm0 concurrently on the capture stream
    cudaEventRecord(ev_fork, 0);
    cudaStreamWaitEvent(s2, ev_fork, 0);
    hist_kernel<<<edge4_blocks, TPB, 0, s2>>>(ei);
    bsum_kernel<<<SCAN_BLOCKS, SCAN_TPB, 0, s2>>>();
    scanout_kernel<<<SCAN_BLOCKS, SCAN_TPB, 0, s2>>>();
    scatter_kernel<<<edge4_blocks, TPB, 0, s2>>>(ei);
    cudaEventRecord(ev_join, s2);

    gemm_kernel<32><<<NN / 8, HID>>>(x, 0, W0, as0, ad0, 0);   // concurrent with CSR

    // join: agg0 needs both CSR and gemm0
    cudaStreamWaitEvent(0, ev_join, 0);

    // Layer 0: out -> bufA
    agg_kernel<false, false><<<node_warp_blocks, TPB>>>(b0, 0, 1, 0, nullptr, nullptr, nullptr);

    // Layer 1: residual(bufA), out -> bufB
    gemm_kernel<HID><<<NN / 8, HID>>>(nullptr, 1, W1, as1, ad1, 1);
    agg_kernel<true, false><<<node_warp_blocks, TPB>>>(b1, 1, 2, 1, nullptr, nullptr, nullptr);

    // Layer 2: residual(bufB), fused final 96->1 projection
    gemm_kernel<HID><<<NN / 8, HID>>>(nullptr, 2, W2, as2, ad2, 2);
    agg_kernel<true, true><<<node_warp_blocks, TPB>>>(b2, 2, 0, 2, Wf, asf, adf);

    // Final layer aggregation (dim 1)
    fagg_kernel<<<node_warp_blocks, TPB>>>(bf, out);
}

// round 16
// speedup vs baseline: 1.0502x; 1.0502x over previous
#include <cuda_runtime.h>

#define NN 50000
#define EE 800000
#define ET 850000   // EE + NN self loops
#define HID 96
#define NEG 0.2f

#define SCAN_TPB 256
#define SCAN_BLOCKS ((NN + SCAN_TPB - 1) / SCAN_TPB)   // 196

// ---------------- scratch (no cudaMalloc allowed) ----------------
__device__ float g_h[NN * HID];
__device__ float g_bufA[NN * HID];
__device__ float g_bufB[NN * HID];
__device__ float g_es[NN];
__device__ float g_ed[NN];
__device__ float2 g_hesf[NN];       // (hf, esf) packed for fagg
__device__ float g_edf[NN];
__device__ unsigned g_max_u[4];     // ordered-float max: slots 0-2 = es per layer, 3 = esf
__device__ int   g_cnt[NN];         // ALWAYS zero at launch entry (module init + scanout self-clean)
__device__ int   g_rowptr[NN + 1];
__device__ int   g_fill[NN];
__device__ int   g_srcbuf[ET];
__device__ int   g_bsum[SCAN_BLOCKS];
__device__ int   g_is64;

__device__ __forceinline__ float* sel_buf(int s) {
    return (s == 1) ? g_bufA : g_bufB;
}

// order-preserving float <-> uint encoding (for atomicMax on floats)
__device__ __forceinline__ unsigned fenc(float f) {
    unsigned u = __float_as_uint(f);
    return (u & 0x80000000u) ? ~u : (u | 0x80000000u);
}
__device__ __forceinline__ float fdec(unsigned e) {
    unsigned u = (e & 0x80000000u) ? (e & 0x7FFFFFFFu) : ~e;
    return __uint_as_float(u);
}

// ---------------- reset: dtype probe + max slots (1 block; must precede gemm0) ----------------
__global__ void rst_kernel(const int* __restrict__ ei32) {
    __shared__ int nz;
    if (threadIdx.x == 0) nz = 0;
    __syncthreads();
    if (ei32[2 * threadIdx.x + 1] != 0) nz = 1;  // benign race
    __syncthreads();
    if (threadIdx.x == 0) g_is64 = (nz == 0) ? 1 : 0;
    if (threadIdx.x < 4) g_max_u[threadIdx.x] = fenc(-1e30f);
}

__device__ __forceinline__ int load_idx(const void* ei, long long pos) {
    if (g_is64) return (int)((const long long*)ei)[pos];
    return ((const int*)ei)[pos];
}

// ---------------- CSR build (R14 form: 1 edge/thread, max parallelism) ----------------
__global__ void hist_kernel(const void* __restrict__ ei) {
    int j = blockIdx.x * blockDim.x + threadIdx.x;
    if (j >= ET) return;
    int dst = (j < EE) ? load_idx(ei, (long long)EE + j) : (j - EE);
    atomicAdd(&g_cnt[dst], 1);
}

__global__ void bsum_kernel() {
    __shared__ int wsum[8];
    int t = threadIdx.x;
    int lane = t & 31, wid = t >> 5;
    int i = blockIdx.x * SCAN_TPB + t;
    int v = (i < NN) ? g_cnt[i] : 0;
#pragma unroll
    for (int off = 16; off; off >>= 1)
        v += __shfl_xor_sync(0xFFFFFFFFu, v, off);
    if (lane == 0) wsum[wid] = v;
    __syncthreads();
    if (t == 0) {
        int s = wsum[0];
#pragma unroll
        for (int w = 1; w < 8; w++) s += wsum[w];
        g_bsum[blockIdx.x] = s;
    }
}

__global__ void scanout_kernel() {
    __shared__ int woff[8];
    __shared__ int wtot[8];
    int t = threadIdx.x;
    int lane = t & 31, wid = t >> 5;

    // block offset = sum of g_bsum[0 .. blockIdx-1]  (shuffle reduce)
    int v = (t < blockIdx.x && t < SCAN_BLOCKS) ? g_bsum[t] : 0;
#pragma unroll
    for (int off = 16; off; off >>= 1)
        v += __shfl_xor_sync(0xFFFFFFFFu, v, off);
    if (lane == 0) woff[wid] = v;

    // per-thread count + warp inclusive scan
    int i = blockIdx.x * SCAN_TPB + t;
    int c = (i < NN) ? g_cnt[i] : 0;
    if (i < NN) g_cnt[i] = 0;   // self-clean: keeps "g_cnt==0 at entry" invariant
    int sc = c;
#pragma unroll
    for (int d = 1; d < 32; d <<= 1) {
        int n = __shfl_up_sync(0xFFFFFFFFu, sc, d);
        if (lane >= d) sc += n;
    }
    if (lane == 31) wtot[wid] = sc;
    __syncthreads();

    int offset = woff[0];
#pragma unroll
    for (int w = 1; w < 8; w++) offset += woff[w];
    int add = 0;
    for (int w = 0; w < wid; w++) add += wtot[w];

    int excl = sc - c + add + offset;
    if (i < NN) {
        g_rowptr[i] = excl;
        g_fill[i]   = excl;
    }
    if (i == NN - 1) g_rowptr[NN] = ET;
}

__global__ void scatter_kernel(const void* __restrict__ ei) {
    int j = blockIdx.x * blockDim.x + threadIdx.x;
    if (j >= ET) return;
    int src, dst;
    if (j < EE) {
        src = load_idx(ei, j);
        dst = load_idx(ei, (long long)EE + j);
    } else {
        src = dst = j - EE;
    }
    int pos = atomicAdd(&g_fill[dst], 1);
    g_srcbuf[pos] = src;
}

// ---------------- GEMM + fused es/ed: 8 nodes/block, 96 threads, f32x2 (R14 form) ----------------
template <int IN>
__global__ void gemm_kernel(const float* __restrict__ x, int in_sel,
                            const float* __restrict__ W,
                            const float* __restrict__ as, const float* __restrict__ ad,
                            int slot) {
    __shared__ __align__(16) float2 xs[IN][4];   // [k][pair]; pair p = nodes (2p, 2p+1)
    __shared__ __align__(16) float sh_h[8][HID];
    __shared__ float sred[3];
    const float* in = (in_sel == 0) ? x : sel_buf(in_sel);
    int nb = blockIdx.x * 8;
    int o  = threadIdx.x;   // 0..95
    int lane = o & 31, wid = o >> 5;
    for (int idx = o; idx < 8 * IN; idx += HID) {
        int n = idx / IN, c = idx % IN;
        ((float*)&xs[c][n >> 1])[n & 1] = in[(nb + n) * IN + c];
    }
    __syncthreads();

    unsigned long long acc0 = 0ull, acc1 = 0ull, acc2 = 0ull, acc3 = 0ull;
#pragma unroll 8
    for (int k = 0; k < IN; k++) {
        float w = W[k * HID + o];
        unsigned long long ww;
        asm("mov.b64 %0, {%1, %1};" : "=l"(ww) : "r"(__float_as_uint(w)));
        ulonglong2 X01 = *reinterpret_cast<const ulonglong2*>(&xs[k][0]);
        ulonglong2 X23 = *reinterpret_cast<const ulonglong2*>(&xs[k][2]);
        asm("fma.rn.f32x2 %0, %1, %2, %0;" : "+l"(acc0) : "l"(X01.x), "l"(ww));
        asm("fma.rn.f32x2 %0, %1, %2, %0;" : "+l"(acc1) : "l"(X01.y), "l"(ww));
        asm("fma.rn.f32x2 %0, %1, %2, %0;" : "+l"(acc2) : "l"(X23.x), "l"(ww));
        asm("fma.rn.f32x2 %0, %1, %2, %0;" : "+l"(acc3) : "l"(X23.y), "l"(ww));
    }

    float h0 = __uint_as_float((unsigned)acc0);
    float h1 = __uint_as_float((unsigned)(acc0 >> 32));
    float h2 = __uint_as_float((unsigned)acc1);
    float h3 = __uint_as_float((unsigned)(acc1 >> 32));
    float h4 = __uint_as_float((unsigned)acc2);
    float h5 = __uint_as_float((unsigned)(acc2 >> 32));
    float h6 = __uint_as_float((unsigned)acc3);
    float h7 = __uint_as_float((unsigned)(acc3 >> 32));
    g_h[(nb + 0) * HID + o] = h0;  sh_h[0][o] = h0;
    g_h[(nb + 1) * HID + o] = h1;  sh_h[1][o] = h1;
    g_h[(nb + 2) * HID + o] = h2;  sh_h[2][o] = h2;
    g_h[(nb + 3) * HID + o] = h3;  sh_h[3][o] = h3;
    g_h[(nb + 4) * HID + o] = h4;  sh_h[4][o] = h4;
    g_h[(nb + 5) * HID + o] = h5;  sh_h[5][o] = h5;
    g_h[(nb + 6) * HID + o] = h6;  sh_h[6][o] = h6;
    g_h[(nb + 7) * HID + o] = h7;  sh_h[7][o] = h7;
    __syncthreads();

    // fused es/ed (warp wid handles nodes wid, wid+3, wid+6)
    float4 a4 = make_float4(0.f, 0.f, 0.f, 0.f), d4 = a4;
    if (lane < 24) {
        a4 = ((const float4*)as)[lane];
        d4 = ((const float4*)ad)[lane];
    }
    float wmax = -1e30f;
    for (int n = wid; n < 8; n += 3) {
        float vs = 0.f, vd = 0.f;
        if (lane < 24) {
            float4 hv = *(const float4*)&sh_h[n][lane * 4];
            vs = hv.x * a4.x + hv.y * a4.y + hv.z * a4.z + hv.w * a4.w;
            vd = hv.x * d4.x + hv.y * d4.y + hv.z * d4.z + hv.w * d4.w;
        }
#pragma unroll
        for (int off = 16; off; off >>= 1) {
            vs += __shfl_xor_sync(0xFFFFFFFFu, vs, off);
            vd += __shfl_xor_sync(0xFFFFFFFFu, vd, off);
        }
        if (lane == 0) {
            g_es[nb + n] = vs;
            g_ed[nb + n] = vd;
            wmax = fmaxf(wmax, vs);
        }
    }
    if (lane == 0) sred[wid] = wmax;
    __syncthreads();
    if (o == 0)
        atomicMax(&g_max_u[slot], fenc(fmaxf(fmaxf(sred[0], sred[1]), sred[2])));
}

// ---------------- aggregation: one warp per destination node (no max pass) ----------------
template <bool RESID, bool FINAL>
__global__ void agg_kernel(const float* __restrict__ b, int resid_sel, int out_sel,
                           int slot,
                           const float* __restrict__ Wf,
                           const float* __restrict__ asf,
                           const float* __restrict__ adf) {
    int node = (blockIdx.x * blockDim.x + threadIdx.x) >> 5;
    int lane = threadIdx.x & 31;
    int beg = g_rowptr[node], end = g_rowptr[node + 1];
    float edst = g_ed[node];
    float m = fdec(g_max_u[slot]) + edst;
    m = (m > 0.f) ? m : NEG * m;

    float a0 = 0.f, a1 = 0.f, a2 = 0.f, ssum = 0.f;
#pragma unroll 4
    for (int j = beg; j < end; j++) {
        int s = g_srcbuf[j];                 // broadcast load
        float e = g_es[s] + edst;            // broadcast load
        e = (e > 0.f) ? e : NEG * e;
        float ex = __expf(e - m);
        const float* hp = g_h + s * HID;
        ssum += ex;
        a0 += ex * hp[lane];
        a1 += ex * hp[lane + 32];
        a2 += ex * hp[lane + 64];
    }
    float inv = 1.f / ssum;
    float o0 = a0 * inv + b[lane];
    float o1 = a1 * inv + b[lane + 32];
    float o2 = a2 * inv + b[lane + 64];
    if (RESID) {
        const float* rp = sel_buf(resid_sel) + node * HID;
        o0 += rp[lane]; o1 += rp[lane + 32]; o2 += rp[lane + 64];
    }
    o0 = fmaxf(o0, 0.f); o1 = fmaxf(o1, 0.f); o2 = fmaxf(o2, 0.f);
    if (FINAL) {
        __shared__ float smaxf[8];
        float v = o0 * Wf[lane] + o1 * Wf[lane + 32] + o2 * Wf[lane + 64];
#pragma unroll
        for (int off = 16; off; off >>= 1)
            v += __shfl_xor_sync(0xFFFFFFFFu, v, off);
        float esf = v * asf[0];
        if (lane == 0) {
            g_hesf[node] = make_float2(v, esf);
            g_edf[node]  = v * adf[0];
            smaxf[threadIdx.x >> 5] = esf;
        }
        __syncthreads();
        if (threadIdx.x == 0) {
            float mm = smaxf[0];
#pragma unroll
            for (int i = 1; i < 8; i++) mm = fmaxf(mm, smaxf[i]);
            atomicMax(&g_max_u[3], fenc(mm));
        }
    } else {
        float* op = sel_buf(out_sel) + node * HID;
        op[lane] = o0; op[lane + 32] = o1; op[lane + 64] = o2;
    }
}

// ---------------- final aggregation (out dim = 1, no max pass, packed gather) ----------------
__global__ void fagg_kernel(const float* __restrict__ bf, float* __restrict__ out) {
    int node = (blockIdx.x * blockDim.x + threadIdx.x) >> 5;
    int lane = threadIdx.x & 31;
    if (node >= NN) return;
    int beg = g_rowptr[node], end = g_rowptr[node + 1];
    float edst = g_edf[node];
    float m = fdec(g_max_u[3]) + edst;
    m = (m > 0.f) ? m : NEG * m;

    float ssum = 0.f, wsum = 0.f;
    for (int j = beg + lane; j < end; j += 32) {
        int s = g_srcbuf[j];
        float2 he = g_hesf[s];               // one LDG.64: (hf, esf)
        float e = he.y + edst;
        e = (e > 0.f) ? e : NEG * e;
        float ex = __expf(e - m);
        ssum += ex;
        wsum += ex * he.x;
    }
#pragma unroll
    for (int off = 16; off; off >>= 1) {
        ssum += __shfl_xor_sync(0xFFFFFFFFu, ssum, off);
        wsum += __shfl_xor_sync(0xFFFFFFFFu, wsum, off);
    }
    if (lane == 0) out[node] = wsum / ssum + bf[0];
}

// ---------------- launch ----------------
extern "C" void kernel_launch(void* const* d_in, const int* in_sizes, int n_in,
                              void* d_out, int out_size) {
    const float* x   = (const float*)d_in[0];
    const void*  ei  = d_in[1];
    const float* W0  = (const float*)d_in[3];
    const float* as0 = (const float*)d_in[4];
    const float* ad0 = (const float*)d_in[5];
    const float* b0  = (const float*)d_in[6];
    const float* W1  = (const float*)d_in[7];
    const float* as1 = (const float*)d_in[8];
    const float* ad1 = (const float*)d_in[9];
    const float* b1  = (const float*)d_in[10];
    const float* W2  = (const float*)d_in[11];
    const float* as2 = (const float*)d_in[12];
    const float* ad2 = (const float*)d_in[13];
    const float* b2  = (const float*)d_in[14];
    const float* Wf  = (const float*)d_in[15];
    const float* asf = (const float*)d_in[16];
    const float* adf = (const float*)d_in[17];
    const float* bf  = (const float*)d_in[18];
    float* out = (float*)d_out;

    // lazily-created side stream + fork/join events
    static cudaStream_t s2 = nullptr;
    static cudaEvent_t ev_fork = nullptr, ev_join = nullptr;
    if (s2 == nullptr) {
        cudaStreamCreateWithFlags(&s2, cudaStreamNonBlocking);
        cudaEventCreateWithFlags(&ev_fork, cudaEventDisableTiming);
        cudaEventCreateWithFlags(&ev_join, cudaEventDisableTiming);
    }

    const int TPB = 256;
    const int edge_blocks = (ET + TPB - 1) / TPB;
    const int node_warp_blocks = (NN * 32 + TPB - 1) / TPB;   // 6250, exact

    // probe + max-slot reset (must precede gemm0's atomicMax AND the CSR chain)
    rst_kernel<<<1, 256>>>((const int*)ei);

    // fork: CSR build on s2, gemm0 concurrently on the capture stream
    cudaEventRecord(ev_fork, 0);
    cudaStreamWaitEvent(s2, ev_fork, 0);
    hist_kernel<<<edge_blocks, TPB, 0, s2>>>(ei);
    bsum_kernel<<<SCAN_BLOCKS, SCAN_TPB, 0, s2>>>();
    scanout_kernel<<<SCAN_BLOCKS, SCAN_TPB, 0, s2>>>();
    scatter_kernel<<<edge_blocks, TPB, 0, s2>>>(ei);
    cudaEventRecord(ev_join, s2);

    gemm_kernel<32><<<NN / 8, HID>>>(x, 0, W0, as0, ad0, 0);   // concurrent with CSR

    // join: agg0 needs both CSR and gemm0
    cudaStreamWaitEvent(0, ev_join, 0);

    // Layer 0: out -> bufA
    agg_kernel<false, false><<<node_warp_blocks, TPB>>>(b0, 0, 1, 0, nullptr, nullptr, nullptr);

    // Layer 1: residual(bufA), out -> bufB
    gemm_kernel<HID><<<NN / 8, HID>>>(nullptr, 1, W1, as1, ad1, 1);
    agg_kernel<true, false><<<node_warp_blocks, TPB>>>(b1, 1, 2, 1, nullptr, nullptr, nullptr);

    // Layer 2: residual(bufB), fused final 96->1 projection
    gemm_kernel<HID><<<NN / 8, HID>>>(nullptr, 2, W2, as2, ad2, 2);
    agg_kernel<true, true><<<node_warp_blocks, TPB>>>(b2, 2, 0, 2, Wf, asf, adf);

    // Final layer aggregation (dim 1)
    fagg_kernel<<<node_warp_blocks, TPB>>>(bf, out);
}